// round 9
// baseline (speedup 1.0000x reference)
#include <cuda_runtime.h>
#include <cuda_bf16.h>
#include <cstdint>

#define B_   2
#define S_   2048
#define D_   1024
#define H_   16
#define DK_  64
#define BH_  (B_ * H_)
#define M_ROWS (B_ * S_)   // 4096

#define QSCALE 0.18033688011112042f   // log2(e)/sqrt(64)

// ---------------- scratch ----------------
__device__ __nv_bfloat16 g_Xhi[M_ROWS * D_];
__device__ __nv_bfloat16 g_Xlo[M_ROWS * D_];
__device__ __nv_bfloat16 g_Wth[3 * D_ * D_];
__device__ __nv_bfloat16 g_Wtl[3 * D_ * D_];
__device__ __nv_bfloat16 g_Qh[BH_ * S_ * DK_];
__device__ __nv_bfloat16 g_Ql[BH_ * S_ * DK_];
__device__ __nv_bfloat16 g_Kh[BH_ * S_ * DK_];
__device__ __nv_bfloat16 g_Kl[BH_ * S_ * DK_];
__device__ __nv_bfloat16 g_Vh[BH_ * S_ * DK_];
__device__ __nv_bfloat16 g_Vl[BH_ * S_ * DK_];

// ---------------- helpers ----------------
__device__ __forceinline__ uint32_t smem_u32(const void* p) {
    uint32_t a;
    asm("{ .reg .u64 t; cvta.to.shared.u64 t, %1; cvt.u32.u64 %0, t; }" : "=r"(a) : "l"(p));
    return a;
}
__device__ __forceinline__ void ldsm4(uint32_t* r, uint32_t addr) {
    asm volatile("ldmatrix.sync.aligned.m8n8.x4.shared.b16 {%0,%1,%2,%3}, [%4];"
        : "=r"(r[0]), "=r"(r[1]), "=r"(r[2]), "=r"(r[3]) : "r"(addr));
}
__device__ __forceinline__ void ldsm4t(uint32_t* r, uint32_t addr) {
    asm volatile("ldmatrix.sync.aligned.m8n8.x4.trans.shared.b16 {%0,%1,%2,%3}, [%4];"
        : "=r"(r[0]), "=r"(r[1]), "=r"(r[2]), "=r"(r[3]) : "r"(addr));
}
__device__ __forceinline__ void mma16816(float* c, const uint32_t* a, const uint32_t* b) {
    asm volatile("mma.sync.aligned.m16n8k16.row.col.f32.bf16.bf16.f32 "
        "{%0,%1,%2,%3}, {%4,%5,%6,%7}, {%8,%9}, {%0,%1,%2,%3};"
        : "+f"(c[0]), "+f"(c[1]), "+f"(c[2]), "+f"(c[3])
        : "r"(a[0]), "r"(a[1]), "r"(a[2]), "r"(a[3]), "r"(b[0]), "r"(b[1]));
}
__device__ __forceinline__ void cpa16(uint32_t d, const void* g) {
    asm volatile("cp.async.cg.shared.global [%0], [%1], 16;" :: "r"(d), "l"(g));
}
#define CP_COMMIT() asm volatile("cp.async.commit_group;" ::: "memory")
#define CP_WAIT0()  asm volatile("cp.async.wait_group 0;" ::: "memory")

// packed bf16 hi/lo split
__device__ __forceinline__ void split2(float a, float b, uint32_t& hi, uint32_t& lo) {
    uint32_t h;
    asm("cvt.rn.bf16x2.f32 %0, %1, %2;" : "=r"(h) : "f"(b), "f"(a));
    const float fa = __uint_as_float(h << 16);
    const float fb = __uint_as_float(h & 0xffff0000u);
    const float ra = a - fa, rb = b - fb;
    uint32_t l;
    asm("cvt.rn.bf16x2.f32 %0, %1, %2;" : "=r"(l) : "f"(rb), "f"(ra));
    hi = h; lo = l;
}

// ---------------------------------------------------------------------------
__global__ __launch_bounds__(256) void split_bf16(
    const float* __restrict__ src, __nv_bfloat16* __restrict__ hi,
    __nv_bfloat16* __restrict__ lo, int n4)
{
    int i = blockIdx.x * blockDim.x + threadIdx.x;
    if (i >= n4) return;
    float4 v = ((const float4*)src)[i];
    uint32_t h0, l0, h1, l1;
    split2(v.x, v.y, h0, l0);
    split2(v.z, v.w, h1, l1);
    uint2 hu = {h0, h1}, lu = {l0, l1};
    ((uint2*)hi)[i] = hu;
    ((uint2*)lo)[i] = lu;
}

// ---------------------------------------------------------------------------
__global__ void transpose_split(const float* __restrict__ W0,
                                const float* __restrict__ W1,
                                const float* __restrict__ W2,
                                __nv_bfloat16* __restrict__ hi,
                                __nv_bfloat16* __restrict__ lo)
{
    __shared__ float t[32][33];
    const float* W = (blockIdx.z == 0) ? W0 : (blockIdx.z == 1) ? W1 : W2;
    const int k = blockIdx.y * 32 + threadIdx.y;
    const int n = blockIdx.x * 32 + threadIdx.x;
    t[threadIdx.y][threadIdx.x] = W[(size_t)k * D_ + n];
    __syncthreads();
    const int nn = blockIdx.x * 32 + threadIdx.y + blockIdx.z * D_;
    const int kk = blockIdx.y * 32 + threadIdx.x;
    float v = t[threadIdx.x][threadIdx.y];
    __nv_bfloat16 h = __float2bfloat16(v);
    __nv_bfloat16 l = __float2bfloat16(v - __bfloat162float(h));
    hi[(size_t)nn * D_ + kk] = h;
    lo[(size_t)nn * D_ + kk] = l;
}

// ---------------------------------------------------------------------------
// HMMA GEMM: unchanged from R7 (2-stage cp.async, 2 CTAs/SM).
// ---------------------------------------------------------------------------
#define GROWB 80
#define SLABB (128 * GROWB)       // 10240
#define STAGEB (4 * SLABB)        // 40960
#define GSMEM (2 * STAGEB)        // 81920

__global__ __launch_bounds__(256, 2) void gemm_tc(
    const __nv_bfloat16* __restrict__ Ah, const __nv_bfloat16* __restrict__ Al,
    const __nv_bfloat16* __restrict__ Bh, const __nv_bfloat16* __restrict__ Bl,
    const float* __restrict__ b0, const float* __restrict__ b1,
    const float* __restrict__ b2, float* __restrict__ Yf,
    __nv_bfloat16* __restrict__ Qh, __nv_bfloat16* __restrict__ Ql,
    __nv_bfloat16* __restrict__ Kh, __nv_bfloat16* __restrict__ Kl,
    __nv_bfloat16* __restrict__ Vh, __nv_bfloat16* __restrict__ Vl,
    int mode)
{
    extern __shared__ __align__(16) unsigned char dsm[];
    const uint32_t s0 = smem_u32(dsm);

    const int tid = threadIdx.x, wid = tid >> 5, lane = tid & 31;
    const int wm = wid >> 2, wn = wid & 3;
    const int bm = blockIdx.y * 128, bn = blockIdx.x * 128;

    const int a4 = tid >> 6, t4 = tid & 63;
    const __nv_bfloat16* gsrc =
        (a4 == 0) ? Ah : (a4 == 1) ? Al : (a4 == 2) ? Bh : Bl;
    gsrc += (size_t)((a4 < 2) ? bm : bn) * 1024;
    const uint32_t slab = s0 + (uint32_t)a4 * SLABB;

    const uint32_t aRow = (uint32_t)(wm * 64 + (lane & 15));
    const uint32_t aCol = (uint32_t)(lane >> 4) * 16;
    const uint32_t bRow0 = (uint32_t)(wn * 32 + ((lane >> 4) & 1) * 8 + (lane & 7));
    const uint32_t bKoff = (uint32_t)((lane >> 3) & 1) * 16;

    float acc[16][4];
#pragma unroll
    for (int i = 0; i < 16; i++)
#pragma unroll
        for (int j = 0; j < 4; j++) acc[i][j] = 0.f;

    auto issue = [&](int ks) {
        const uint32_t st = slab + (uint32_t)(ks & 1) * STAGEB;
        const __nv_bfloat16* g = gsrc + ks * 32;
#pragma unroll
        for (int p = 0; p < 8; p++) {
            const int idx = p * 64 + t4;
            const int row = idx >> 2, ch = idx & 3;
            cpa16(st + (uint32_t)row * GROWB + (uint32_t)ch * 16,
                  g + (size_t)row * 1024 + ch * 8);
        }
        CP_COMMIT();
    };

    issue(0);

    for (int ks = 0; ks < 32; ks++) {
        CP_WAIT0();
        __syncthreads();
        if (ks + 1 < 32) issue(ks + 1);

        const uint32_t sb  = s0 + (uint32_t)(ks & 1) * STAGEB;
        const uint32_t SAh = sb, SAl = sb + SLABB;
        const uint32_t SBh = sb + 2 * SLABB, SBl = sb + 3 * SLABB;

#pragma unroll
        for (int h = 0; h < 2; h++) {
            uint32_t fA[4][4], fB[4][2];
            const uint32_t hoff = (uint32_t)h * 32;
#pragma unroll
            for (int mt = 0; mt < 4; mt++)
                ldsm4(fA[mt], SAh + (aRow + (uint32_t)(mt * 16)) * GROWB + hoff + aCol);
#pragma unroll
            for (int g = 0; g < 2; g++) {
                uint32_t r[4];
                ldsm4(r, SBh + (bRow0 + (uint32_t)(g * 16)) * GROWB + hoff + bKoff);
                fB[g * 2][0] = r[0]; fB[g * 2][1] = r[1];
                fB[g * 2 + 1][0] = r[2]; fB[g * 2 + 1][1] = r[3];
            }
#pragma unroll
            for (int mt = 0; mt < 4; mt++)
#pragma unroll
                for (int nt = 0; nt < 4; nt++)
                    mma16816(acc[mt * 4 + nt], fA[mt], fB[nt]);
#pragma unroll
            for (int mt = 0; mt < 4; mt++)
                ldsm4(fA[mt], SAl + (aRow + (uint32_t)(mt * 16)) * GROWB + hoff + aCol);
#pragma unroll
            for (int mt = 0; mt < 4; mt++)
#pragma unroll
                for (int nt = 0; nt < 4; nt++)
                    mma16816(acc[mt * 4 + nt], fA[mt], fB[nt]);
#pragma unroll
            for (int g = 0; g < 2; g++) {
                uint32_t r[4];
                ldsm4(r, SBl + (bRow0 + (uint32_t)(g * 16)) * GROWB + hoff + bKoff);
                fB[g * 2][0] = r[0]; fB[g * 2][1] = r[1];
                fB[g * 2 + 1][0] = r[2]; fB[g * 2 + 1][1] = r[3];
            }
#pragma unroll
            for (int mt = 0; mt < 4; mt++)
                ldsm4(fA[mt], SAh + (aRow + (uint32_t)(mt * 16)) * GROWB + hoff + aCol);
#pragma unroll
            for (int mt = 0; mt < 4; mt++)
#pragma unroll
                for (int nt = 0; nt < 4; nt++)
                    mma16816(acc[mt * 4 + nt], fA[mt], fB[nt]);
        }
    }

    // ---- epilogue ----
    const int qr = lane >> 2, qc = (lane & 3) * 2;
    const int proj = bn >> 10;
    const float* bias = (proj == 0) ? b0 : (proj == 1) ? b1 : b2;
    const float scale = (mode == 1 && proj == 0) ? QSCALE : 1.0f;
    __nv_bfloat16* Yh = (proj == 0) ? Qh : (proj == 1) ? Kh : Vh;
    __nv_bfloat16* Yl = (proj == 0) ? Ql : (proj == 1) ? Kl : Vl;
    const int bnl = bn & 1023;

#pragma unroll
    for (int mt = 0; mt < 4; mt++) {
#pragma unroll
        for (int nt = 0; nt < 4; nt++) {
            const float* a4p = acc[mt * 4 + nt];
            const int r0 = bm + wm * 64 + mt * 16 + qr;
            const int cn = bnl + wn * 32 + nt * 8 + qc;
            const float bv0 = bias[cn], bv1 = bias[cn + 1];
            if (mode == 0) {
                float2 v0 = {a4p[0] + bv0, a4p[1] + bv1};
                float2 v1 = {a4p[2] + bv0, a4p[3] + bv1};
                *(float2*)(Yf + (size_t)r0 * 1024 + cn) = v0;
                *(float2*)(Yf + (size_t)(r0 + 8) * 1024 + cn) = v1;
            } else {
                const float w0 = (a4p[0] + bv0) * scale, w1 = (a4p[1] + bv1) * scale;
                const float w2 = (a4p[2] + bv0) * scale, w3 = (a4p[3] + bv1) * scale;
                const int h  = cn >> 6, dk = cn & 63;
                const int b0i = r0 >> 11, s0i = r0 & 2047;
                const int b1i = (r0 + 8) >> 11, s1i = (r0 + 8) & 2047;
                const size_t o0 = (((size_t)(b0i * H_ + h)) * S_ + s0i) * DK_ + dk;
                const size_t o1 = (((size_t)(b1i * H_ + h)) * S_ + s1i) * DK_ + dk;
                uint32_t h0, l0, h1, l1;
                split2(w0, w1, h0, l0);
                split2(w2, w3, h1, l1);
                *(uint32_t*)(Yh + o0) = h0; *(uint32_t*)(Yl + o0) = l0;
                *(uint32_t*)(Yh + o1) = h1; *(uint32_t*)(Yl + o1) = l1;
            }
        }
    }
}

// ---------------------------------------------------------------------------
// Flash attention (causal): 256 threads / 128 q-rows per CTA, 2 CTAs/SM.
// Q stays in smem; fragments reloaded per key tile (frees 32 regs -> <=128).
// smem 96KB: Qh@0, Ql@16384; KV stage st at 32768+st*32768:
//   Kh+0, Kl+8192, Vh+16384, Vl+24576.
// ---------------------------------------------------------------------------
#define ASMEM 98304

__global__ __launch_bounds__(256, 2) void flash_attn_tc(
    const __nv_bfloat16* __restrict__ Qh, const __nv_bfloat16* __restrict__ Ql,
    const __nv_bfloat16* __restrict__ Kh, const __nv_bfloat16* __restrict__ Kl,
    const __nv_bfloat16* __restrict__ Vh, const __nv_bfloat16* __restrict__ Vl,
    __nv_bfloat16* __restrict__ Ohi, __nv_bfloat16* __restrict__ Olo)
{
    extern __shared__ __align__(16) unsigned char sm[];
    const uint32_t s0 = smem_u32(sm);

    const int tid = threadIdx.x, wid = tid >> 5, lane = tid & 31;
    const int qt = 15 - blockIdx.x;          // heavy tiles first
    const int bh = blockIdx.y;
    const int qbase = qt * 128;
    const int njt = 2 * (qt + 1);
    const int rb = wid * 16;

    // ---- stage Q (128 rows, hi+lo) ----
    {
        const int arr = tid >> 7;            // 0=hi 1=lo
        const int t2 = tid & 127;
        const __nv_bfloat16* base = (arr ? Ql : Qh) + ((size_t)bh * S_ + qbase) * DK_;
        const uint32_t db = (uint32_t)arr * 16384;
#pragma unroll
        for (int p = 0; p < 8; p++) {
            const int idx = p * 128 + t2;
            const int row = idx >> 3, ch = idx & 7;
            *(uint4*)(sm + db + (uint32_t)row * 128 + (uint32_t)((ch ^ (row & 7)) << 4)) =
                *(const uint4*)(base + (size_t)row * 64 + ch * 8);
        }
    }

    // ---- KV copy geometry: 64 threads per array ----
    const int a4 = tid >> 6, t4 = tid & 63;
    const __nv_bfloat16* kvsrc =
        (a4 == 0) ? Kh : (a4 == 1) ? Kl : (a4 == 2) ? Vh : Vl;
    kvsrc += (size_t)bh * S_ * DK_;
    const uint32_t kvdst = s0 + 32768 + (uint32_t)a4 * 8192;

    {
        const __nv_bfloat16* g = kvsrc;
#pragma unroll
        for (int p = 0; p < 8; p++) {
            const int idx = p * 64 + t4;
            const int row = idx >> 3, ch = idx & 7;
            cpa16(kvdst + (uint32_t)row * 128 + (uint32_t)((ch ^ (row & 7)) << 4),
                  g + (size_t)row * 64 + ch * 8);
        }
    }
    CP_COMMIT();
    __syncthreads();    // Q staged (and KV tile 0 in flight)

    // Q fragment addresses (recomputed loads each key tile; addr precomputed)
    const int qrow = rb + (lane & 15);
    const int qr7 = qrow & 7;
    uint32_t qaddr[4];
#pragma unroll
    for (int kk = 0; kk < 4; kk++)
        qaddr[kk] = s0 + (uint32_t)qrow * 128 +
                    (uint32_t)(((2 * kk + (lane >> 4)) ^ qr7) << 4);

    float m_i[2] = {-1e30f, -1e30f};
    float l_i[2] = {0.f, 0.f};
    float oac[8][4];
#pragma unroll
    for (int t = 0; t < 8; t++)
#pragma unroll
        for (int e = 0; e < 4; e++) oac[t][e] = 0.f;

    for (int jt = 0; jt < njt; jt++) {
        CP_WAIT0();
        __syncthreads();
        const uint32_t bb = s0 + 32768 + (uint32_t)(jt & 1) * 32768;

        if (jt + 1 < njt) {
            const __nv_bfloat16* g = kvsrc + (size_t)(jt + 1) * 64 * 64;
            const uint32_t db = s0 + 32768 + (uint32_t)((jt + 1) & 1) * 32768 +
                                (uint32_t)a4 * 8192;
#pragma unroll
            for (int p = 0; p < 8; p++) {
                const int idx = p * 64 + t4;
                const int row = idx >> 3, ch = idx & 7;
                cpa16(db + (uint32_t)row * 128 + (uint32_t)((ch ^ (row & 7)) << 4),
                      g + (size_t)row * 64 + ch * 8);
            }
            CP_COMMIT();
        }

        float sc[8][4];
#pragma unroll
        for (int t = 0; t < 8; t++)
#pragma unroll
            for (int e = 0; e < 4; e++) sc[t][e] = 0.f;

        // ---- scores: Q frags reloaded from smem per kk ----
#pragma unroll
        for (int kk = 0; kk < 4; kk++) {
            uint32_t qfh[4], qfl[4];
            ldsm4(qfh, qaddr[kk]);
            ldsm4(qfl, qaddr[kk] + 16384);
#pragma unroll
            for (int j = 0; j < 4; j++) {
                const int krow = 16 * j + (lane & 7) + ((lane & 16) >> 1);
                const uint32_t ka = bb + (uint32_t)krow * 128 +
                    (uint32_t)(((2 * kk + ((lane >> 3) & 1)) ^ (krow & 7)) << 4);
                uint32_t bhf[4], blf[4];
                ldsm4(bhf, ka);
                ldsm4(blf, ka + 8192);
                mma16816(sc[2 * j],     qfh, bhf + 0);
                mma16816(sc[2 * j + 1], qfh, bhf + 2);
                mma16816(sc[2 * j],     qfh, blf + 0);
                mma16816(sc[2 * j + 1], qfh, blf + 2);
                mma16816(sc[2 * j],     qfl, bhf + 0);
                mma16816(sc[2 * j + 1], qfl, bhf + 2);
            }
        }

        // ---- causal mask (last two key tiles) ----
        if (jt >= njt - 2) {
            const int kb = jt * 64;
#pragma unroll
            for (int t = 0; t < 8; t++)
#pragma unroll
                for (int e = 0; e < 4; e++) {
                    const int kg = kb + t * 8 + 2 * (lane & 3) + (e & 1);
                    const int qg = qbase + rb + (lane >> 2) + (e >> 1) * 8;
                    if (kg > qg) sc[t][e] = -1e9f;
                }
        }

        // ---- online softmax ----
#pragma unroll
        for (int h = 0; h < 2; h++) {
            float mr = -1e30f;
#pragma unroll
            for (int t = 0; t < 8; t++)
                mr = fmaxf(mr, fmaxf(sc[t][2 * h], sc[t][2 * h + 1]));
            mr = fmaxf(mr, __shfl_xor_sync(0xffffffffu, mr, 1));
            mr = fmaxf(mr, __shfl_xor_sync(0xffffffffu, mr, 2));
            const float mn = fmaxf(m_i[h], mr);
            const float alpha = exp2f(m_i[h] - mn);
            m_i[h] = mn;
            float rs = 0.f;
#pragma unroll
            for (int t = 0; t < 8; t++) {
                sc[t][2 * h]     = exp2f(sc[t][2 * h] - mn);
                sc[t][2 * h + 1] = exp2f(sc[t][2 * h + 1] - mn);
                rs += sc[t][2 * h] + sc[t][2 * h + 1];
            }
            rs += __shfl_xor_sync(0xffffffffu, rs, 1);
            rs += __shfl_xor_sync(0xffffffffu, rs, 2);
            l_i[h] = l_i[h] * alpha + rs;
#pragma unroll
            for (int t = 0; t < 8; t++) {
                oac[t][2 * h]     *= alpha;
                oac[t][2 * h + 1] *= alpha;
            }
        }

        // ---- PV ----
#pragma unroll
        for (int kk = 0; kk < 4; kk++) {
            uint32_t pah[4], pal[4];
            split2(sc[2 * kk][0],     sc[2 * kk][1],     pah[0], pal[0]);
            split2(sc[2 * kk][2],     sc[2 * kk][3],     pah[1], pal[1]);
            split2(sc[2 * kk + 1][0], sc[2 * kk + 1][1], pah[2], pal[2]);
            split2(sc[2 * kk + 1][2], sc[2 * kk + 1][3], pah[3], pal[3]);

            const int vrow = 16 * kk + (lane & 15);
            const int vr7 = vrow & 7;
#pragma unroll
            for (int j = 0; j < 4; j++) {
                const uint32_t va = bb + 16384 + (uint32_t)vrow * 128 +
                    (uint32_t)(((2 * j + (lane >> 4)) ^ vr7) << 4);
                uint32_t vhf[4], vlf[4];
                ldsm4t(vhf, va);
                ldsm4t(vlf, va + 8192);
                mma16816(oac[2 * j],     pah, vhf + 0);
                mma16816(oac[2 * j + 1], pah, vhf + 2);
                mma16816(oac[2 * j],     pah, vlf + 0);
                mma16816(oac[2 * j + 1], pah, vlf + 2);
                mma16816(oac[2 * j],     pal, vhf + 0);
                mma16816(oac[2 * j + 1], pal, vhf + 2);
            }
        }
    }

    // ---- epilogue ----
    const int bb_ = bh >> 4, hh = bh & 15;
#pragma unroll
    for (int h = 0; h < 2; h++) {
        const float invl = 1.f / l_i[h];
        const int rg = qbase + rb + (lane >> 2) + 8 * h;
        const size_t mrow = (size_t)(bb_ * 2048 + rg) * 1024;
#pragma unroll
        for (int t = 0; t < 8; t++) {
            const float v0 = oac[t][2 * h] * invl;
            const float v1 = oac[t][2 * h + 1] * invl;
            const int col = hh * 64 + t * 8 + 2 * (lane & 3);
            uint32_t hi, lo;
            split2(v0, v1, hi, lo);
            *(uint32_t*)(Ohi + mrow + col) = hi;
            *(uint32_t*)(Olo + mrow + col) = lo;
        }
    }
}

// ---------------------------------------------------------------------------
extern "C" void kernel_launch(void* const* d_in, const int* in_sizes, int n_in,
                              void* d_out, int out_size)
{
    const float* x  = (const float*)d_in[0];
    const float* Wq = (const float*)d_in[2];
    const float* bq = (const float*)d_in[3];
    const float* Wk = (const float*)d_in[4];
    const float* bk = (const float*)d_in[5];
    const float* Wv = (const float*)d_in[6];
    const float* bv = (const float*)d_in[7];
    const float* Wo = (const float*)d_in[8];
    const float* bo = (const float*)d_in[9];

    __nv_bfloat16 *xh, *xl, *wth, *wtl, *qh, *ql, *kh, *kl, *vh, *vl;
    cudaGetSymbolAddress((void**)&xh, g_Xhi);
    cudaGetSymbolAddress((void**)&xl, g_Xlo);
    cudaGetSymbolAddress((void**)&wth, g_Wth);
    cudaGetSymbolAddress((void**)&wtl, g_Wtl);
    cudaGetSymbolAddress((void**)&qh, g_Qh);
    cudaGetSymbolAddress((void**)&ql, g_Ql);
    cudaGetSymbolAddress((void**)&kh, g_Kh);
    cudaGetSymbolAddress((void**)&kl, g_Kl);
    cudaGetSymbolAddress((void**)&vh, g_Vh);
    cudaGetSymbolAddress((void**)&vl, g_Vl);

    const int n4 = M_ROWS * D_ / 4;
    const dim3 tb(32, 32);

    cudaFuncSetAttribute(gemm_tc, cudaFuncAttributeMaxDynamicSharedMemorySize, GSMEM);
    cudaFuncSetAttribute(flash_attn_tc, cudaFuncAttributeMaxDynamicSharedMemorySize, ASMEM);

    split_bf16<<<(n4 + 255) / 256, 256>>>(x, xh, xl, n4);
    transpose_split<<<dim3(32, 32, 3), tb>>>(Wq, Wk, Wv, wth, wtl);

    gemm_tc<<<dim3(24, 32), 256, GSMEM>>>(xh, xl, wth, wtl, bq, bk, bv,
                                          nullptr, qh, ql, kh, kl, vh, vl, 1);

    flash_attn_tc<<<dim3(16, BH_), 256, ASMEM>>>(qh, ql, kh, kl, vh, vl, xh, xl);

    transpose_split<<<dim3(32, 32, 1), tb>>>(Wo, Wo, Wo, wth, wtl);
    gemm_tc<<<dim3(8, 32), 256, GSMEM>>>(xh, xl, wth, wtl, bo, bo, bo,
                                         (float*)d_out, nullptr, nullptr,
                                         nullptr, nullptr, nullptr, nullptr, 0);
}

// round 10
// speedup vs baseline: 1.0863x; 1.0863x over previous
#include <cuda_runtime.h>
#include <cuda_bf16.h>
#include <cuda_fp16.h>
#include <cstdint>

#define B_   2
#define S_   2048
#define D_   1024
#define H_   16
#define DK_  64
#define BH_  (B_ * H_)
#define M_ROWS (B_ * S_)   // 4096

#define QSCALE 0.18033688011112042f   // log2(e)/sqrt(64)

// ---------------- scratch ----------------
__device__ __half g_Xhi[M_ROWS * D_];      // fp16 split inputs / ctx
__device__ __half g_Xlo[M_ROWS * D_];
__device__ __half g_Wth[3 * D_ * D_];
__device__ __half g_Wtl[3 * D_ * D_];
__device__ __nv_bfloat16 g_Qh[BH_ * S_ * DK_];   // attention stays bf16
__device__ __nv_bfloat16 g_Ql[BH_ * S_ * DK_];
__device__ __nv_bfloat16 g_Kh[BH_ * S_ * DK_];
__device__ __nv_bfloat16 g_Kl[BH_ * S_ * DK_];
__device__ __nv_bfloat16 g_Vh[BH_ * S_ * DK_];
__device__ __nv_bfloat16 g_Vl[BH_ * S_ * DK_];

// ---------------- helpers ----------------
__device__ __forceinline__ uint32_t smem_u32(const void* p) {
    uint32_t a;
    asm("{ .reg .u64 t; cvta.to.shared.u64 t, %1; cvt.u32.u64 %0, t; }" : "=r"(a) : "l"(p));
    return a;
}
__device__ __forceinline__ void ldsm4(uint32_t* r, uint32_t addr) {
    asm volatile("ldmatrix.sync.aligned.m8n8.x4.shared.b16 {%0,%1,%2,%3}, [%4];"
        : "=r"(r[0]), "=r"(r[1]), "=r"(r[2]), "=r"(r[3]) : "r"(addr));
}
__device__ __forceinline__ void ldsm4t(uint32_t* r, uint32_t addr) {
    asm volatile("ldmatrix.sync.aligned.m8n8.x4.trans.shared.b16 {%0,%1,%2,%3}, [%4];"
        : "=r"(r[0]), "=r"(r[1]), "=r"(r[2]), "=r"(r[3]) : "r"(addr));
}
// bf16 x bf16 -> fp32
__device__ __forceinline__ void mma16816(float* c, const uint32_t* a, const uint32_t* b) {
    asm volatile("mma.sync.aligned.m16n8k16.row.col.f32.bf16.bf16.f32 "
        "{%0,%1,%2,%3}, {%4,%5,%6,%7}, {%8,%9}, {%0,%1,%2,%3};"
        : "+f"(c[0]), "+f"(c[1]), "+f"(c[2]), "+f"(c[3])
        : "r"(a[0]), "r"(a[1]), "r"(a[2]), "r"(a[3]), "r"(b[0]), "r"(b[1]));
}
// fp16 x fp16 -> fp32
__device__ __forceinline__ void mma16816h(float* c, const uint32_t* a, const uint32_t* b) {
    asm volatile("mma.sync.aligned.m16n8k16.row.col.f32.f16.f16.f32 "
        "{%0,%1,%2,%3}, {%4,%5,%6,%7}, {%8,%9}, {%0,%1,%2,%3};"
        : "+f"(c[0]), "+f"(c[1]), "+f"(c[2]), "+f"(c[3])
        : "r"(a[0]), "r"(a[1]), "r"(a[2]), "r"(a[3]), "r"(b[0]), "r"(b[1]));
}
// fp16 x fp16 -> fp16 (half-width accumulator)
__device__ __forceinline__ void mma16816hh(uint32_t* c, const uint32_t* a, const uint32_t* b) {
    asm volatile("mma.sync.aligned.m16n8k16.row.col.f16.f16.f16.f16 "
        "{%0,%1}, {%2,%3,%4,%5}, {%6,%7}, {%0,%1};"
        : "+r"(c[0]), "+r"(c[1])
        : "r"(a[0]), "r"(a[1]), "r"(a[2]), "r"(a[3]), "r"(b[0]), "r"(b[1]));
}
__device__ __forceinline__ void cpa16(uint32_t d, const void* g) {
    asm volatile("cp.async.cg.shared.global [%0], [%1], 16;" :: "r"(d), "l"(g));
}
#define CP_COMMIT() asm volatile("cp.async.commit_group;" ::: "memory")
#define CP_WAIT0()  asm volatile("cp.async.wait_group 0;" ::: "memory")

// packed bf16 hi/lo split (attention P + QKV epilogue)
__device__ __forceinline__ void split2(float a, float b, uint32_t& hi, uint32_t& lo) {
    uint32_t h;
    asm("cvt.rn.bf16x2.f32 %0, %1, %2;" : "=r"(h) : "f"(b), "f"(a));
    const float fa = __uint_as_float(h << 16);
    const float fb = __uint_as_float(h & 0xffff0000u);
    const float ra = a - fa, rb = b - fb;
    uint32_t l;
    asm("cvt.rn.bf16x2.f32 %0, %1, %2;" : "=r"(l) : "f"(rb), "f"(ra));
    hi = h; lo = l;
}
// packed fp16 hi/lo split (GEMM operands)
__device__ __forceinline__ void split2h(float a, float b, uint32_t& hi, uint32_t& lo) {
    uint32_t h;
    asm("cvt.rn.f16x2.f32 %0, %1, %2;" : "=r"(h) : "f"(b), "f"(a));
    const __half2 hp = *(const __half2*)&h;
    const float fa = __half2float(__low2half(hp));
    const float fb = __half2float(__high2half(hp));
    const float ra = a - fa, rb = b - fb;
    uint32_t l;
    asm("cvt.rn.f16x2.f32 %0, %1, %2;" : "=r"(l) : "f"(rb), "f"(ra));
    hi = h; lo = l;
}

// ---------------------------------------------------------------------------
__global__ __launch_bounds__(256) void split_f16(
    const float* __restrict__ src, __half* __restrict__ hi,
    __half* __restrict__ lo, int n4)
{
    int i = blockIdx.x * blockDim.x + threadIdx.x;
    if (i >= n4) return;
    float4 v = ((const float4*)src)[i];
    uint32_t h0, l0, h1, l1;
    split2h(v.x, v.y, h0, l0);
    split2h(v.z, v.w, h1, l1);
    uint2 hu = {h0, h1}, lu = {l0, l1};
    ((uint2*)hi)[i] = hu;
    ((uint2*)lo)[i] = lu;
}

// ---------------------------------------------------------------------------
__global__ void transpose_split(const float* __restrict__ W0,
                                const float* __restrict__ W1,
                                const float* __restrict__ W2,
                                __half* __restrict__ hi,
                                __half* __restrict__ lo)
{
    __shared__ float t[32][33];
    const float* W = (blockIdx.z == 0) ? W0 : (blockIdx.z == 1) ? W1 : W2;
    const int k = blockIdx.y * 32 + threadIdx.y;
    const int n = blockIdx.x * 32 + threadIdx.x;
    t[threadIdx.y][threadIdx.x] = W[(size_t)k * D_ + n];
    __syncthreads();
    const int nn = blockIdx.x * 32 + threadIdx.y + blockIdx.z * D_;
    const int kk = blockIdx.y * 32 + threadIdx.x;
    float v = t[threadIdx.x][threadIdx.y];
    __half h = __float2half_rn(v);
    __half l = __float2half_rn(v - __half2float(h));
    hi[(size_t)nn * D_ + kk] = h;
    lo[(size_t)nn * D_ + kk] = l;
}

// ---------------------------------------------------------------------------
// HMMA GEMM, fp16 splits: pass1 hi*hi fp32-acc; passes 2,3 (corrections)
// fp16-acc (half-width accumulator -> hypothesized 2x HMMA rate).
// 2-stage cp.async, 2 CTAs/SM target.
// ---------------------------------------------------------------------------
#define GROWB 80
#define SLABB (128 * GROWB)       // 10240
#define STAGEB (4 * SLABB)        // 40960
#define GSMEM (2 * STAGEB)        // 81920

__global__ __launch_bounds__(256, 2) void gemm_tc(
    const __half* __restrict__ Ah, const __half* __restrict__ Al,
    const __half* __restrict__ Bh, const __half* __restrict__ Bl,
    const float* __restrict__ b0, const float* __restrict__ b1,
    const float* __restrict__ b2, float* __restrict__ Yf,
    __nv_bfloat16* __restrict__ Qh, __nv_bfloat16* __restrict__ Ql,
    __nv_bfloat16* __restrict__ Kh, __nv_bfloat16* __restrict__ Kl,
    __nv_bfloat16* __restrict__ Vh, __nv_bfloat16* __restrict__ Vl,
    int mode)
{
    extern __shared__ __align__(16) unsigned char dsm[];
    const uint32_t s0 = smem_u32(dsm);

    const int tid = threadIdx.x, wid = tid >> 5, lane = tid & 31;
    const int wm = wid >> 2, wn = wid & 3;
    const int bm = blockIdx.y * 128, bn = blockIdx.x * 128;

    const int a4 = tid >> 6, t4 = tid & 63;
    const __half* gsrc =
        (a4 == 0) ? Ah : (a4 == 1) ? Al : (a4 == 2) ? Bh : Bl;
    gsrc += (size_t)((a4 < 2) ? bm : bn) * 1024;
    const uint32_t slab = s0 + (uint32_t)a4 * SLABB;

    const uint32_t aRow = (uint32_t)(wm * 64 + (lane & 15));
    const uint32_t aCol = (uint32_t)(lane >> 4) * 16;
    const uint32_t bRow0 = (uint32_t)(wn * 32 + ((lane >> 4) & 1) * 8 + (lane & 7));
    const uint32_t bKoff = (uint32_t)((lane >> 3) & 1) * 16;

    float acc[16][4];
    uint32_t facc[16][2];
#pragma unroll
    for (int i = 0; i < 16; i++) {
#pragma unroll
        for (int j = 0; j < 4; j++) acc[i][j] = 0.f;
        facc[i][0] = 0u; facc[i][1] = 0u;
    }

    auto issue = [&](int ks) {
        const uint32_t st = slab + (uint32_t)(ks & 1) * STAGEB;
        const __half* g = gsrc + ks * 32;
#pragma unroll
        for (int p = 0; p < 8; p++) {
            const int idx = p * 64 + t4;
            const int row = idx >> 2, ch = idx & 3;
            cpa16(st + (uint32_t)row * GROWB + (uint32_t)ch * 16,
                  g + (size_t)row * 1024 + ch * 8);
        }
        CP_COMMIT();
    };

    issue(0);

    for (int ks = 0; ks < 32; ks++) {
        CP_WAIT0();
        __syncthreads();
        if (ks + 1 < 32) issue(ks + 1);

        const uint32_t sb  = s0 + (uint32_t)(ks & 1) * STAGEB;
        const uint32_t SAh = sb, SAl = sb + SLABB;
        const uint32_t SBh = sb + 2 * SLABB, SBl = sb + 3 * SLABB;

#pragma unroll
        for (int h = 0; h < 2; h++) {
            uint32_t fA[4][4], fB[4][2];
            const uint32_t hoff = (uint32_t)h * 32;
            // Ah + Bh
#pragma unroll
            for (int mt = 0; mt < 4; mt++)
                ldsm4(fA[mt], SAh + (aRow + (uint32_t)(mt * 16)) * GROWB + hoff + aCol);
#pragma unroll
            for (int g = 0; g < 2; g++) {
                uint32_t r[4];
                ldsm4(r, SBh + (bRow0 + (uint32_t)(g * 16)) * GROWB + hoff + bKoff);
                fB[g * 2][0] = r[0]; fB[g * 2][1] = r[1];
                fB[g * 2 + 1][0] = r[2]; fB[g * 2 + 1][1] = r[3];
            }
            // pass 1: Ah x Bh (fp32 acc)
#pragma unroll
            for (int mt = 0; mt < 4; mt++)
#pragma unroll
                for (int nt = 0; nt < 4; nt++)
                    mma16816h(acc[mt * 4 + nt], fA[mt], fB[nt]);
            // pass 2: Al x Bh (fp16 acc)
#pragma unroll
            for (int mt = 0; mt < 4; mt++)
                ldsm4(fA[mt], SAl + (aRow + (uint32_t)(mt * 16)) * GROWB + hoff + aCol);
#pragma unroll
            for (int mt = 0; mt < 4; mt++)
#pragma unroll
                for (int nt = 0; nt < 4; nt++)
                    mma16816hh(facc[mt * 4 + nt], fA[mt], fB[nt]);
            // pass 3: Ah x Bl (fp16 acc)
#pragma unroll
            for (int g = 0; g < 2; g++) {
                uint32_t r[4];
                ldsm4(r, SBl + (bRow0 + (uint32_t)(g * 16)) * GROWB + hoff + bKoff);
                fB[g * 2][0] = r[0]; fB[g * 2][1] = r[1];
                fB[g * 2 + 1][0] = r[2]; fB[g * 2 + 1][1] = r[3];
            }
#pragma unroll
            for (int mt = 0; mt < 4; mt++)
                ldsm4(fA[mt], SAh + (aRow + (uint32_t)(mt * 16)) * GROWB + hoff + aCol);
#pragma unroll
            for (int mt = 0; mt < 4; mt++)
#pragma unroll
                for (int nt = 0; nt < 4; nt++)
                    mma16816hh(facc[mt * 4 + nt], fA[mt], fB[nt]);
        }
    }

    // ---- epilogue: main + fp16 corrections + bias ----
    const int qr = lane >> 2, qc = (lane & 3) * 2;
    const int proj = bn >> 10;
    const float* bias = (proj == 0) ? b0 : (proj == 1) ? b1 : b2;
    const float scale = (mode == 1 && proj == 0) ? QSCALE : 1.0f;
    __nv_bfloat16* Yh = (proj == 0) ? Qh : (proj == 1) ? Kh : Vh;
    __nv_bfloat16* Yl = (proj == 0) ? Ql : (proj == 1) ? Kl : Vl;
    const int bnl = bn & 1023;

#pragma unroll
    for (int mt = 0; mt < 4; mt++) {
#pragma unroll
        for (int nt = 0; nt < 4; nt++) {
            const int i = mt * 4 + nt;
            const __half2 c01 = *(const __half2*)&facc[i][0];
            const __half2 c23 = *(const __half2*)&facc[i][1];
            const float v0f = acc[i][0] + __half2float(__low2half(c01));
            const float v1f = acc[i][1] + __half2float(__high2half(c01));
            const float v2f = acc[i][2] + __half2float(__low2half(c23));
            const float v3f = acc[i][3] + __half2float(__high2half(c23));
            const int r0 = bm + wm * 64 + mt * 16 + qr;
            const int cn = bnl + wn * 32 + nt * 8 + qc;
            const float bv0 = bias[cn], bv1 = bias[cn + 1];
            if (mode == 0) {
                float2 v0 = {v0f + bv0, v1f + bv1};
                float2 v1 = {v2f + bv0, v3f + bv1};
                *(float2*)(Yf + (size_t)r0 * 1024 + cn) = v0;
                *(float2*)(Yf + (size_t)(r0 + 8) * 1024 + cn) = v1;
            } else {
                const float w0 = (v0f + bv0) * scale, w1 = (v1f + bv1) * scale;
                const float w2 = (v2f + bv0) * scale, w3 = (v3f + bv1) * scale;
                const int h  = cn >> 6, dk = cn & 63;
                const int b0i = r0 >> 11, s0i = r0 & 2047;
                const int b1i = (r0 + 8) >> 11, s1i = (r0 + 8) & 2047;
                const size_t o0 = (((size_t)(b0i * H_ + h)) * S_ + s0i) * DK_ + dk;
                const size_t o1 = (((size_t)(b1i * H_ + h)) * S_ + s1i) * DK_ + dk;
                uint32_t h0, l0, h1, l1;
                split2(w0, w1, h0, l0);
                split2(w2, w3, h1, l1);
                *(uint32_t*)(Yh + o0) = h0; *(uint32_t*)(Yl + o0) = l0;
                *(uint32_t*)(Yh + o1) = h1; *(uint32_t*)(Yl + o1) = l1;
            }
        }
    }
}

// ---------------------------------------------------------------------------
// Flash attention (causal): R8 config (128 thr / 64 q-rows, 2 CTAs/SM).
// bf16 3-pass HMMA; epilogue writes ctx as fp16 hi/lo for the out-projection.
// ---------------------------------------------------------------------------
#define ASMEM 81920

__global__ __launch_bounds__(128, 2) void flash_attn_tc(
    const __nv_bfloat16* __restrict__ Qh, const __nv_bfloat16* __restrict__ Ql,
    const __nv_bfloat16* __restrict__ Kh, const __nv_bfloat16* __restrict__ Kl,
    const __nv_bfloat16* __restrict__ Vh, const __nv_bfloat16* __restrict__ Vl,
    __half* __restrict__ Ohi, __half* __restrict__ Olo)
{
    extern __shared__ __align__(16) unsigned char sm[];
    const uint32_t s0 = smem_u32(sm);

    const int tid = threadIdx.x, wid = tid >> 5, lane = tid & 31;
    const int qt = 31 - blockIdx.x;
    const int bh = blockIdx.y;
    const int qbase = qt * 64;
    const int njt = qt + 1;
    const int rb = wid * 16;

    {
        const int arr = tid >> 6;
        const int t2 = tid & 63;
        const __nv_bfloat16* base = (arr ? Ql : Qh) + ((size_t)bh * S_ + qbase) * DK_;
        const uint32_t db = (uint32_t)arr * 8192;
#pragma unroll
        for (int p = 0; p < 8; p++) {
            const int idx = p * 64 + t2;
            const int row = idx >> 3, ch = idx & 7;
            *(uint4*)(sm + db + (uint32_t)row * 128 + (uint32_t)((ch ^ (row & 7)) << 4)) =
                *(const uint4*)(base + (size_t)row * 64 + ch * 8);
        }
    }
    __syncthreads();

    uint32_t qfh[4][4], qfl[4][4];
    {
        const int row = rb + (lane & 15);
        const int r7 = row & 7;
#pragma unroll
        for (int kk = 0; kk < 4; kk++) {
            const uint32_t a = s0 + (uint32_t)row * 128 +
                (uint32_t)(((2 * kk + (lane >> 4)) ^ r7) << 4);
            ldsm4(qfh[kk], a);
            ldsm4(qfl[kk], a + 8192);
        }
    }
    __syncthreads();

    const int a4  = tid >> 5;
    const int t5  = tid & 31;
    const __nv_bfloat16* kvsrc =
        (a4 == 0) ? Kh : (a4 == 1) ? Kl : (a4 == 2) ? Vh : Vl;
    kvsrc += (size_t)bh * S_ * DK_;
    const uint32_t kvdst = s0 + 16384 + (uint32_t)a4 * 8192;

    {
        const __nv_bfloat16* g = kvsrc;
#pragma unroll
        for (int p = 0; p < 16; p++) {
            const int idx = p * 32 + t5;
            const int row = idx >> 3, ch = idx & 7;
            cpa16(kvdst + (uint32_t)row * 128 + (uint32_t)((ch ^ (row & 7)) << 4),
                  g + (size_t)row * 64 + ch * 8);
        }
    }
    CP_COMMIT();

    float m_i[2] = {-1e30f, -1e30f};
    float l_i[2] = {0.f, 0.f};
    float oac[8][4];
#pragma unroll
    for (int t = 0; t < 8; t++)
#pragma unroll
        for (int e = 0; e < 4; e++) oac[t][e] = 0.f;

    for (int jt = 0; jt < njt; jt++) {
        CP_WAIT0();
        __syncthreads();
        const uint32_t bb = s0 + 16384 + (uint32_t)(jt & 1) * 32768;

        if (jt + 1 < njt) {
            const __nv_bfloat16* g = kvsrc + (size_t)(jt + 1) * 64 * 64;
            const uint32_t db = kvdst + (uint32_t)((jt + 1) & 1) * 32768;
#pragma unroll
            for (int p = 0; p < 16; p++) {
                const int idx = p * 32 + t5;
                const int row = idx >> 3, ch = idx & 7;
                cpa16(db + (uint32_t)row * 128 + (uint32_t)((ch ^ (row & 7)) << 4),
                      g + (size_t)row * 64 + ch * 8);
            }
            CP_COMMIT();
        }

        float sc[8][4];
#pragma unroll
        for (int t = 0; t < 8; t++)
#pragma unroll
            for (int e = 0; e < 4; e++) sc[t][e] = 0.f;

#pragma unroll
        for (int kk = 0; kk < 4; kk++) {
#pragma unroll
            for (int j = 0; j < 4; j++) {
                const int krow = 16 * j + (lane & 7) + ((lane & 16) >> 1);
                const uint32_t ka = bb + (uint32_t)krow * 128 +
                    (uint32_t)(((2 * kk + ((lane >> 3) & 1)) ^ (krow & 7)) << 4);
                uint32_t bhf[4], blf[4];
                ldsm4(bhf, ka);
                ldsm4(blf, ka + 8192);
                mma16816(sc[2 * j],     qfh[kk], bhf + 0);
                mma16816(sc[2 * j + 1], qfh[kk], bhf + 2);
                mma16816(sc[2 * j],     qfh[kk], blf + 0);
                mma16816(sc[2 * j + 1], qfh[kk], blf + 2);
                mma16816(sc[2 * j],     qfl[kk], bhf + 0);
                mma16816(sc[2 * j + 1], qfl[kk], bhf + 2);
            }
        }

        if (jt == njt - 1) {
#pragma unroll
            for (int t = 0; t < 8; t++)
#pragma unroll
                for (int e = 0; e < 4; e++) {
                    const int kg = t * 8 + 2 * (lane & 3) + (e & 1);
                    const int qg = rb + (lane >> 2) + (e >> 1) * 8;
                    if (kg > qg) sc[t][e] = -1e9f;
                }
        }

#pragma unroll
        for (int h = 0; h < 2; h++) {
            float mr = -1e30f;
#pragma unroll
            for (int t = 0; t < 8; t++)
                mr = fmaxf(mr, fmaxf(sc[t][2 * h], sc[t][2 * h + 1]));
            mr = fmaxf(mr, __shfl_xor_sync(0xffffffffu, mr, 1));
            mr = fmaxf(mr, __shfl_xor_sync(0xffffffffu, mr, 2));
            const float mn = fmaxf(m_i[h], mr);
            if (__any_sync(0xffffffffu, mn != m_i[h])) {
                const float alpha = exp2f(m_i[h] - mn);
                m_i[h] = mn;
                l_i[h] *= alpha;
#pragma unroll
                for (int t = 0; t < 8; t++) {
                    oac[t][2 * h]     *= alpha;
                    oac[t][2 * h + 1] *= alpha;
                }
            }
            float rs = 0.f;
#pragma unroll
            for (int t = 0; t < 8; t++) {
                sc[t][2 * h]     = exp2f(sc[t][2 * h] - mn);
                sc[t][2 * h + 1] = exp2f(sc[t][2 * h + 1] - mn);
                rs += sc[t][2 * h] + sc[t][2 * h + 1];
            }
            rs += __shfl_xor_sync(0xffffffffu, rs, 1);
            rs += __shfl_xor_sync(0xffffffffu, rs, 2);
            l_i[h] += rs;
        }

#pragma unroll
        for (int kk = 0; kk < 4; kk++) {
            uint32_t pah[4], pal[4];
            split2(sc[2 * kk][0],     sc[2 * kk][1],     pah[0], pal[0]);
            split2(sc[2 * kk][2],     sc[2 * kk][3],     pah[1], pal[1]);
            split2(sc[2 * kk + 1][0], sc[2 * kk + 1][1], pah[2], pal[2]);
            split2(sc[2 * kk + 1][2], sc[2 * kk + 1][3], pah[3], pal[3]);

            const int vrow = 16 * kk + (lane & 15);
            const int vr7 = vrow & 7;
#pragma unroll
            for (int j = 0; j < 4; j++) {
                const uint32_t va = bb + 16384 + (uint32_t)vrow * 128 +
                    (uint32_t)(((2 * j + (lane >> 4)) ^ vr7) << 4);
                uint32_t vhf[4], vlf[4];
                ldsm4t(vhf, va);
                ldsm4t(vlf, va + 8192);
                mma16816(oac[2 * j],     pah, vhf + 0);
                mma16816(oac[2 * j + 1], pah, vhf + 2);
                mma16816(oac[2 * j],     pah, vlf + 0);
                mma16816(oac[2 * j + 1], pah, vlf + 2);
                mma16816(oac[2 * j],     pal, vhf + 0);
                mma16816(oac[2 * j + 1], pal, vhf + 2);
            }
        }
    }

    const int bb_ = bh >> 4, hh = bh & 15;
#pragma unroll
    for (int h = 0; h < 2; h++) {
        const float invl = 1.f / l_i[h];
        const int rg = qbase + rb + (lane >> 2) + 8 * h;
        const size_t mrow = (size_t)(bb_ * 2048 + rg) * 1024;
#pragma unroll
        for (int t = 0; t < 8; t++) {
            const float v0 = oac[t][2 * h] * invl;
            const float v1 = oac[t][2 * h + 1] * invl;
            const int col = hh * 64 + t * 8 + 2 * (lane & 3);
            uint32_t hi, lo;
            split2h(v0, v1, hi, lo);        // fp16 ctx for out-projection
            *(uint32_t*)(Ohi + mrow + col) = hi;
            *(uint32_t*)(Olo + mrow + col) = lo;
        }
    }
}

// ---------------------------------------------------------------------------
extern "C" void kernel_launch(void* const* d_in, const int* in_sizes, int n_in,
                              void* d_out, int out_size)
{
    const float* x  = (const float*)d_in[0];
    const float* Wq = (const float*)d_in[2];
    const float* bq = (const float*)d_in[3];
    const float* Wk = (const float*)d_in[4];
    const float* bk = (const float*)d_in[5];
    const float* Wv = (const float*)d_in[6];
    const float* bv = (const float*)d_in[7];
    const float* Wo = (const float*)d_in[8];
    const float* bo = (const float*)d_in[9];

    __half *xh, *xl, *wth, *wtl;
    __nv_bfloat16 *qh, *ql, *kh, *kl, *vh, *vl;
    cudaGetSymbolAddress((void**)&xh, g_Xhi);
    cudaGetSymbolAddress((void**)&xl, g_Xlo);
    cudaGetSymbolAddress((void**)&wth, g_Wth);
    cudaGetSymbolAddress((void**)&wtl, g_Wtl);
    cudaGetSymbolAddress((void**)&qh, g_Qh);
    cudaGetSymbolAddress((void**)&ql, g_Ql);
    cudaGetSymbolAddress((void**)&kh, g_Kh);
    cudaGetSymbolAddress((void**)&kl, g_Kl);
    cudaGetSymbolAddress((void**)&vh, g_Vh);
    cudaGetSymbolAddress((void**)&vl, g_Vl);

    const int n4 = M_ROWS * D_ / 4;
    const dim3 tb(32, 32);

    cudaFuncSetAttribute(gemm_tc, cudaFuncAttributeMaxDynamicSharedMemorySize, GSMEM);
    cudaFuncSetAttribute(flash_attn_tc, cudaFuncAttributeMaxDynamicSharedMemorySize, ASMEM);

    split_f16<<<(n4 + 255) / 256, 256>>>(x, xh, xl, n4);
    transpose_split<<<dim3(32, 32, 3), tb>>>(Wq, Wk, Wv, wth, wtl);

    gemm_tc<<<dim3(24, 32), 256, GSMEM>>>(xh, xl, wth, wtl, bq, bk, bv,
                                          nullptr, qh, ql, kh, kl, vh, vl, 1);

    flash_attn_tc<<<dim3(32, BH_), 128, ASMEM>>>(qh, ql, kh, kl, vh, vl, xh, xl);

    transpose_split<<<dim3(32, 32, 1), tb>>>(Wo, Wo, Wo, wth, wtl);
    gemm_tc<<<dim3(8, 32), 256, GSMEM>>>(xh, xl, wth, wtl, bo, bo, bo,
                                         (float*)d_out, nullptr, nullptr,
                                         nullptr, nullptr, nullptr, nullptr, 0);
}

// round 11
// speedup vs baseline: 1.0900x; 1.0033x over previous
#include <cuda_runtime.h>
#include <cuda_bf16.h>
#include <cuda_fp16.h>
#include <cstdint>

#define B_   2
#define S_   2048
#define D_   1024
#define H_   16
#define DK_  64
#define BH_  (B_ * H_)
#define M_ROWS (B_ * S_)   // 4096

#define QSCALE 0.18033688011112042f   // log2(e)/sqrt(64)

// ---------------- scratch ----------------
__device__ __half g_Xhi[M_ROWS * D_];
__device__ __half g_Xlo[M_ROWS * D_];
__device__ __half g_Wth[3 * D_ * D_];
__device__ __half g_Wtl[3 * D_ * D_];
__device__ __nv_bfloat16 g_Qh[BH_ * S_ * DK_];
__device__ __nv_bfloat16 g_Ql[BH_ * S_ * DK_];
__device__ __nv_bfloat16 g_Kh[BH_ * S_ * DK_];
__device__ __nv_bfloat16 g_Kl[BH_ * S_ * DK_];
__device__ __nv_bfloat16 g_Vh[BH_ * S_ * DK_];
__device__ __nv_bfloat16 g_Vl[BH_ * S_ * DK_];

// ---------------- helpers ----------------
__device__ __forceinline__ uint32_t smem_u32(const void* p) {
    uint32_t a;
    asm("{ .reg .u64 t; cvta.to.shared.u64 t, %1; cvt.u32.u64 %0, t; }" : "=r"(a) : "l"(p));
    return a;
}
__device__ __forceinline__ void ldsm4(uint32_t* r, uint32_t addr) {
    asm volatile("ldmatrix.sync.aligned.m8n8.x4.shared.b16 {%0,%1,%2,%3}, [%4];"
        : "=r"(r[0]), "=r"(r[1]), "=r"(r[2]), "=r"(r[3]) : "r"(addr));
}
__device__ __forceinline__ void ldsm4t(uint32_t* r, uint32_t addr) {
    asm volatile("ldmatrix.sync.aligned.m8n8.x4.trans.shared.b16 {%0,%1,%2,%3}, [%4];"
        : "=r"(r[0]), "=r"(r[1]), "=r"(r[2]), "=r"(r[3]) : "r"(addr));
}
// bf16 x bf16 -> fp32
__device__ __forceinline__ void mma16816(float* c, const uint32_t* a, const uint32_t* b) {
    asm volatile("mma.sync.aligned.m16n8k16.row.col.f32.bf16.bf16.f32 "
        "{%0,%1,%2,%3}, {%4,%5,%6,%7}, {%8,%9}, {%0,%1,%2,%3};"
        : "+f"(c[0]), "+f"(c[1]), "+f"(c[2]), "+f"(c[3])
        : "r"(a[0]), "r"(a[1]), "r"(a[2]), "r"(a[3]), "r"(b[0]), "r"(b[1]));
}
// fp16 x fp16 -> fp32
__device__ __forceinline__ void mma16816h(float* c, const uint32_t* a, const uint32_t* b) {
    asm volatile("mma.sync.aligned.m16n8k16.row.col.f32.f16.f16.f32 "
        "{%0,%1,%2,%3}, {%4,%5,%6,%7}, {%8,%9}, {%0,%1,%2,%3};"
        : "+f"(c[0]), "+f"(c[1]), "+f"(c[2]), "+f"(c[3])
        : "r"(a[0]), "r"(a[1]), "r"(a[2]), "r"(a[3]), "r"(b[0]), "r"(b[1]));
}
// fp16 x fp16 -> fp16
__device__ __forceinline__ void mma16816hh(uint32_t* c, const uint32_t* a, const uint32_t* b) {
    asm volatile("mma.sync.aligned.m16n8k16.row.col.f16.f16.f16.f16 "
        "{%0,%1}, {%2,%3,%4,%5}, {%6,%7}, {%0,%1};"
        : "+r"(c[0]), "+r"(c[1])
        : "r"(a[0]), "r"(a[1]), "r"(a[2]), "r"(a[3]), "r"(b[0]), "r"(b[1]));
}
__device__ __forceinline__ void cpa16(uint32_t d, const void* g) {
    asm volatile("cp.async.cg.shared.global [%0], [%1], 16;" :: "r"(d), "l"(g));
}
#define CP_COMMIT() asm volatile("cp.async.commit_group;" ::: "memory")
#define CP_WAIT0()  asm volatile("cp.async.wait_group 0;" ::: "memory")

// packed bf16 hi/lo split
__device__ __forceinline__ void split2(float a, float b, uint32_t& hi, uint32_t& lo) {
    uint32_t h;
    asm("cvt.rn.bf16x2.f32 %0, %1, %2;" : "=r"(h) : "f"(b), "f"(a));
    const float fa = __uint_as_float(h << 16);
    const float fb = __uint_as_float(h & 0xffff0000u);
    const float ra = a - fa, rb = b - fb;
    uint32_t l;
    asm("cvt.rn.bf16x2.f32 %0, %1, %2;" : "=r"(l) : "f"(rb), "f"(ra));
    hi = h; lo = l;
}
// packed fp16 hi/lo split
__device__ __forceinline__ void split2h(float a, float b, uint32_t& hi, uint32_t& lo) {
    uint32_t h;
    asm("cvt.rn.f16x2.f32 %0, %1, %2;" : "=r"(h) : "f"(b), "f"(a));
    const __half2 hp = *(const __half2*)&h;
    const float fa = __half2float(__low2half(hp));
    const float fb = __half2float(__high2half(hp));
    const float ra = a - fa, rb = b - fb;
    uint32_t l;
    asm("cvt.rn.f16x2.f32 %0, %1, %2;" : "=r"(l) : "f"(rb), "f"(ra));
    hi = h; lo = l;
}

// ---------------------------------------------------------------------------
__global__ __launch_bounds__(256) void split_f16(
    const float* __restrict__ src, __half* __restrict__ hi,
    __half* __restrict__ lo, int n4)
{
    int i = blockIdx.x * blockDim.x + threadIdx.x;
    if (i >= n4) return;
    float4 v = ((const float4*)src)[i];
    uint32_t h0, l0, h1, l1;
    split2h(v.x, v.y, h0, l0);
    split2h(v.z, v.w, h1, l1);
    uint2 hu = {h0, h1}, lu = {l0, l1};
    ((uint2*)hi)[i] = hu;
    ((uint2*)lo)[i] = lu;
}

// ---------------------------------------------------------------------------
__global__ void transpose_split(const float* __restrict__ W0,
                                const float* __restrict__ W1,
                                const float* __restrict__ W2,
                                __half* __restrict__ hi,
                                __half* __restrict__ lo)
{
    __shared__ float t[32][33];
    const float* W = (blockIdx.z == 0) ? W0 : (blockIdx.z == 1) ? W1 : W2;
    const int k = blockIdx.y * 32 + threadIdx.y;
    const int n = blockIdx.x * 32 + threadIdx.x;
    t[threadIdx.y][threadIdx.x] = W[(size_t)k * D_ + n];
    __syncthreads();
    const int nn = blockIdx.x * 32 + threadIdx.y + blockIdx.z * D_;
    const int kk = blockIdx.y * 32 + threadIdx.x;
    float v = t[threadIdx.x][threadIdx.y];
    __half h = __float2half_rn(v);
    __half l = __float2half_rn(v - __half2float(h));
    hi[(size_t)nn * D_ + kk] = h;
    lo[(size_t)nn * D_ + kk] = l;
}

// ---------------------------------------------------------------------------
// HMMA GEMM (unchanged from R10): fp16 splits, pass1 fp32-acc, corrections
// fp16-acc; 2-stage cp.async; 2 CTAs/SM.
// ---------------------------------------------------------------------------
#define GROWB 80
#define SLABB (128 * GROWB)
#define STAGEB (4 * SLABB)
#define GSMEM (2 * STAGEB)

__global__ __launch_bounds__(256, 2) void gemm_tc(
    const __half* __restrict__ Ah, const __half* __restrict__ Al,
    const __half* __restrict__ Bh, const __half* __restrict__ Bl,
    const float* __restrict__ b0, const float* __restrict__ b1,
    const float* __restrict__ b2, float* __restrict__ Yf,
    __nv_bfloat16* __restrict__ Qh, __nv_bfloat16* __restrict__ Ql,
    __nv_bfloat16* __restrict__ Kh, __nv_bfloat16* __restrict__ Kl,
    __nv_bfloat16* __restrict__ Vh, __nv_bfloat16* __restrict__ Vl,
    int mode)
{
    extern __shared__ __align__(16) unsigned char dsm[];
    const uint32_t s0 = smem_u32(dsm);

    const int tid = threadIdx.x, wid = tid >> 5, lane = tid & 31;
    const int wm = wid >> 2, wn = wid & 3;
    const int bm = blockIdx.y * 128, bn = blockIdx.x * 128;

    const int a4 = tid >> 6, t4 = tid & 63;
    const __half* gsrc =
        (a4 == 0) ? Ah : (a4 == 1) ? Al : (a4 == 2) ? Bh : Bl;
    gsrc += (size_t)((a4 < 2) ? bm : bn) * 1024;
    const uint32_t slab = s0 + (uint32_t)a4 * SLABB;

    const uint32_t aRow = (uint32_t)(wm * 64 + (lane & 15));
    const uint32_t aCol = (uint32_t)(lane >> 4) * 16;
    const uint32_t bRow0 = (uint32_t)(wn * 32 + ((lane >> 4) & 1) * 8 + (lane & 7));
    const uint32_t bKoff = (uint32_t)((lane >> 3) & 1) * 16;

    float acc[16][4];
    uint32_t facc[16][2];
#pragma unroll
    for (int i = 0; i < 16; i++) {
#pragma unroll
        for (int j = 0; j < 4; j++) acc[i][j] = 0.f;
        facc[i][0] = 0u; facc[i][1] = 0u;
    }

    auto issue = [&](int ks) {
        const uint32_t st = slab + (uint32_t)(ks & 1) * STAGEB;
        const __half* g = gsrc + ks * 32;
#pragma unroll
        for (int p = 0; p < 8; p++) {
            const int idx = p * 64 + t4;
            const int row = idx >> 2, ch = idx & 3;
            cpa16(st + (uint32_t)row * GROWB + (uint32_t)ch * 16,
                  g + (size_t)row * 1024 + ch * 8);
        }
        CP_COMMIT();
    };

    issue(0);

    for (int ks = 0; ks < 32; ks++) {
        CP_WAIT0();
        __syncthreads();
        if (ks + 1 < 32) issue(ks + 1);

        const uint32_t sb  = s0 + (uint32_t)(ks & 1) * STAGEB;
        const uint32_t SAh = sb, SAl = sb + SLABB;
        const uint32_t SBh = sb + 2 * SLABB, SBl = sb + 3 * SLABB;

#pragma unroll
        for (int h = 0; h < 2; h++) {
            uint32_t fA[4][4], fB[4][2];
            const uint32_t hoff = (uint32_t)h * 32;
#pragma unroll
            for (int mt = 0; mt < 4; mt++)
                ldsm4(fA[mt], SAh + (aRow + (uint32_t)(mt * 16)) * GROWB + hoff + aCol);
#pragma unroll
            for (int g = 0; g < 2; g++) {
                uint32_t r[4];
                ldsm4(r, SBh + (bRow0 + (uint32_t)(g * 16)) * GROWB + hoff + bKoff);
                fB[g * 2][0] = r[0]; fB[g * 2][1] = r[1];
                fB[g * 2 + 1][0] = r[2]; fB[g * 2 + 1][1] = r[3];
            }
#pragma unroll
            for (int mt = 0; mt < 4; mt++)
#pragma unroll
                for (int nt = 0; nt < 4; nt++)
                    mma16816h(acc[mt * 4 + nt], fA[mt], fB[nt]);
#pragma unroll
            for (int mt = 0; mt < 4; mt++)
                ldsm4(fA[mt], SAl + (aRow + (uint32_t)(mt * 16)) * GROWB + hoff + aCol);
#pragma unroll
            for (int mt = 0; mt < 4; mt++)
#pragma unroll
                for (int nt = 0; nt < 4; nt++)
                    mma16816hh(facc[mt * 4 + nt], fA[mt], fB[nt]);
#pragma unroll
            for (int g = 0; g < 2; g++) {
                uint32_t r[4];
                ldsm4(r, SBl + (bRow0 + (uint32_t)(g * 16)) * GROWB + hoff + bKoff);
                fB[g * 2][0] = r[0]; fB[g * 2][1] = r[1];
                fB[g * 2 + 1][0] = r[2]; fB[g * 2 + 1][1] = r[3];
            }
#pragma unroll
            for (int mt = 0; mt < 4; mt++)
                ldsm4(fA[mt], SAh + (aRow + (uint32_t)(mt * 16)) * GROWB + hoff + aCol);
#pragma unroll
            for (int mt = 0; mt < 4; mt++)
#pragma unroll
                for (int nt = 0; nt < 4; nt++)
                    mma16816hh(facc[mt * 4 + nt], fA[mt], fB[nt]);
        }
    }

    // ---- epilogue ----
    const int qr = lane >> 2, qc = (lane & 3) * 2;
    const int proj = bn >> 10;
    const float* bias = (proj == 0) ? b0 : (proj == 1) ? b1 : b2;
    const float scale = (mode == 1 && proj == 0) ? QSCALE : 1.0f;
    __nv_bfloat16* Yh = (proj == 0) ? Qh : (proj == 1) ? Kh : Vh;
    __nv_bfloat16* Yl = (proj == 0) ? Ql : (proj == 1) ? Kl : Vl;
    const int bnl = bn & 1023;

#pragma unroll
    for (int mt = 0; mt < 4; mt++) {
#pragma unroll
        for (int nt = 0; nt < 4; nt++) {
            const int i = mt * 4 + nt;
            const __half2 c01 = *(const __half2*)&facc[i][0];
            const __half2 c23 = *(const __half2*)&facc[i][1];
            const float v0f = acc[i][0] + __half2float(__low2half(c01));
            const float v1f = acc[i][1] + __half2float(__high2half(c01));
            const float v2f = acc[i][2] + __half2float(__low2half(c23));
            const float v3f = acc[i][3] + __half2float(__high2half(c23));
            const int r0 = bm + wm * 64 + mt * 16 + qr;
            const int cn = bnl + wn * 32 + nt * 8 + qc;
            const float bv0 = bias[cn], bv1 = bias[cn + 1];
            if (mode == 0) {
                float2 v0 = {v0f + bv0, v1f + bv1};
                float2 v1 = {v2f + bv0, v3f + bv1};
                *(float2*)(Yf + (size_t)r0 * 1024 + cn) = v0;
                *(float2*)(Yf + (size_t)(r0 + 8) * 1024 + cn) = v1;
            } else {
                const float w0 = (v0f + bv0) * scale, w1 = (v1f + bv1) * scale;
                const float w2 = (v2f + bv0) * scale, w3 = (v3f + bv1) * scale;
                const int h  = cn >> 6, dk = cn & 63;
                const int b0i = r0 >> 11, s0i = r0 & 2047;
                const int b1i = (r0 + 8) >> 11, s1i = (r0 + 8) & 2047;
                const size_t o0 = (((size_t)(b0i * H_ + h)) * S_ + s0i) * DK_ + dk;
                const size_t o1 = (((size_t)(b1i * H_ + h)) * S_ + s1i) * DK_ + dk;
                uint32_t h0, l0, h1, l1;
                split2(w0, w1, h0, l0);
                split2(w2, w3, h1, l1);
                *(uint32_t*)(Yh + o0) = h0; *(uint32_t*)(Yl + o0) = l0;
                *(uint32_t*)(Yh + o1) = h1; *(uint32_t*)(Yl + o1) = l1;
            }
        }
    }
}

// ---------------------------------------------------------------------------
// Flash attention (causal): 128 thr / 64 q-rows, 2 CTAs/SM.
// R11: PV accumulates into per-tile pvacc (decouples PV MMAs from the
// alpha/l/oac chain); Q-lo fragments reloaded per tile (register budget).
// ---------------------------------------------------------------------------
#define ASMEM 81920

__global__ __launch_bounds__(128, 2) void flash_attn_tc(
    const __nv_bfloat16* __restrict__ Qh, const __nv_bfloat16* __restrict__ Ql,
    const __nv_bfloat16* __restrict__ Kh, const __nv_bfloat16* __restrict__ Kl,
    const __nv_bfloat16* __restrict__ Vh, const __nv_bfloat16* __restrict__ Vl,
    __half* __restrict__ Ohi, __half* __restrict__ Olo)
{
    extern __shared__ __align__(16) unsigned char sm[];
    const uint32_t s0 = smem_u32(sm);

    const int tid = threadIdx.x, wid = tid >> 5, lane = tid & 31;
    const int qt = 31 - blockIdx.x;
    const int bh = blockIdx.y;
    const int qbase = qt * 64;
    const int njt = qt + 1;
    const int rb = wid * 16;

    // ---- stage Q (hi@0, lo@8192) ----
    {
        const int arr = tid >> 6;
        const int t2 = tid & 63;
        const __nv_bfloat16* base = (arr ? Ql : Qh) + ((size_t)bh * S_ + qbase) * DK_;
        const uint32_t db = (uint32_t)arr * 8192;
#pragma unroll
        for (int p = 0; p < 8; p++) {
            const int idx = p * 64 + t2;
            const int row = idx >> 3, ch = idx & 7;
            *(uint4*)(sm + db + (uint32_t)row * 128 + (uint32_t)((ch ^ (row & 7)) << 4)) =
                *(const uint4*)(base + (size_t)row * 64 + ch * 8);
        }
    }
    __syncthreads();

    // Q-hi fragments resident; Q-lo addresses precomputed (reload per tile)
    uint32_t qfh[4][4], qaddr[4];
    {
        const int row = rb + (lane & 15);
        const int r7 = row & 7;
#pragma unroll
        for (int kk = 0; kk < 4; kk++) {
            qaddr[kk] = s0 + (uint32_t)row * 128 +
                        (uint32_t)(((2 * kk + (lane >> 4)) ^ r7) << 4);
            ldsm4(qfh[kk], qaddr[kk]);
        }
    }
    __syncthreads();

    const int a4  = tid >> 5;
    const int t5  = tid & 31;
    const __nv_bfloat16* kvsrc =
        (a4 == 0) ? Kh : (a4 == 1) ? Kl : (a4 == 2) ? Vh : Vl;
    kvsrc += (size_t)bh * S_ * DK_;
    const uint32_t kvdst = s0 + 16384 + (uint32_t)a4 * 8192;

    {
        const __nv_bfloat16* g = kvsrc;
#pragma unroll
        for (int p = 0; p < 16; p++) {
            const int idx = p * 32 + t5;
            const int row = idx >> 3, ch = idx & 7;
            cpa16(kvdst + (uint32_t)row * 128 + (uint32_t)((ch ^ (row & 7)) << 4),
                  g + (size_t)row * 64 + ch * 8);
        }
    }
    CP_COMMIT();

    float m_i[2] = {-1e30f, -1e30f};
    float l_i[2] = {0.f, 0.f};
    float oac[8][4];
#pragma unroll
    for (int t = 0; t < 8; t++)
#pragma unroll
        for (int e = 0; e < 4; e++) oac[t][e] = 0.f;

    for (int jt = 0; jt < njt; jt++) {
        CP_WAIT0();
        __syncthreads();
        const uint32_t bb = s0 + 16384 + (uint32_t)(jt & 1) * 32768;

        if (jt + 1 < njt) {
            const __nv_bfloat16* g = kvsrc + (size_t)(jt + 1) * 64 * 64;
            const uint32_t db = kvdst + (uint32_t)((jt + 1) & 1) * 32768;
#pragma unroll
            for (int p = 0; p < 16; p++) {
                const int idx = p * 32 + t5;
                const int row = idx >> 3, ch = idx & 7;
                cpa16(db + (uint32_t)row * 128 + (uint32_t)((ch ^ (row & 7)) << 4),
                      g + (size_t)row * 64 + ch * 8);
            }
            CP_COMMIT();
        }

        // ---- scores ----
        float sc[8][4];
#pragma unroll
        for (int t = 0; t < 8; t++)
#pragma unroll
            for (int e = 0; e < 4; e++) sc[t][e] = 0.f;

#pragma unroll
        for (int kk = 0; kk < 4; kk++) {
            uint32_t qfl[4];
            ldsm4(qfl, qaddr[kk] + 8192);     // Q-lo reload (non-resident)
#pragma unroll
            for (int j = 0; j < 4; j++) {
                const int krow = 16 * j + (lane & 7) + ((lane & 16) >> 1);
                const uint32_t ka = bb + (uint32_t)krow * 128 +
                    (uint32_t)(((2 * kk + ((lane >> 3) & 1)) ^ (krow & 7)) << 4);
                uint32_t bhf[4], blf[4];
                ldsm4(bhf, ka);
                ldsm4(blf, ka + 8192);
                mma16816(sc[2 * j],     qfh[kk], bhf + 0);
                mma16816(sc[2 * j + 1], qfh[kk], bhf + 2);
                mma16816(sc[2 * j],     qfh[kk], blf + 0);
                mma16816(sc[2 * j + 1], qfh[kk], blf + 2);
                mma16816(sc[2 * j],     qfl,     bhf + 0);
                mma16816(sc[2 * j + 1], qfl,     bhf + 2);
            }
        }

        if (jt == njt - 1) {
#pragma unroll
            for (int t = 0; t < 8; t++)
#pragma unroll
                for (int e = 0; e < 4; e++) {
                    const int kg = t * 8 + 2 * (lane & 3) + (e & 1);
                    const int qg = rb + (lane >> 2) + (e >> 1) * 8;
                    if (kg > qg) sc[t][e] = -1e9f;
                }
        }

        // ---- softmax phase 1: row max + exp2 only (minimal chain to PV) ----
        float mn[2];
#pragma unroll
        for (int h = 0; h < 2; h++) {
            float mr = -1e30f;
#pragma unroll
            for (int t = 0; t < 8; t++)
                mr = fmaxf(mr, fmaxf(sc[t][2 * h], sc[t][2 * h + 1]));
            mr = fmaxf(mr, __shfl_xor_sync(0xffffffffu, mr, 1));
            mr = fmaxf(mr, __shfl_xor_sync(0xffffffffu, mr, 2));
            mn[h] = fmaxf(m_i[h], mr);
#pragma unroll
            for (int t = 0; t < 8; t++) {
                sc[t][2 * h]     = exp2f(sc[t][2 * h] - mn[h]);
                sc[t][2 * h + 1] = exp2f(sc[t][2 * h + 1] - mn[h]);
            }
        }

        // ---- PV into fresh pvacc (independent of alpha/l/oac chain) ----
        float pvacc[8][4];
#pragma unroll
        for (int t = 0; t < 8; t++)
#pragma unroll
            for (int e = 0; e < 4; e++) pvacc[t][e] = 0.f;

#pragma unroll
        for (int kk = 0; kk < 4; kk++) {
            uint32_t pah[4], pal[4];
            split2(sc[2 * kk][0],     sc[2 * kk][1],     pah[0], pal[0]);
            split2(sc[2 * kk][2],     sc[2 * kk][3],     pah[1], pal[1]);
            split2(sc[2 * kk + 1][0], sc[2 * kk + 1][1], pah[2], pal[2]);
            split2(sc[2 * kk + 1][2], sc[2 * kk + 1][3], pah[3], pal[3]);

            const int vrow = 16 * kk + (lane & 15);
            const int vr7 = vrow & 7;
#pragma unroll
            for (int j = 0; j < 4; j++) {
                const uint32_t va = bb + 16384 + (uint32_t)vrow * 128 +
                    (uint32_t)(((2 * j + (lane >> 4)) ^ vr7) << 4);
                uint32_t vhf[4], vlf[4];
                ldsm4t(vhf, va);
                ldsm4t(vlf, va + 8192);
                mma16816(pvacc[2 * j],     pah, vhf + 0);
                mma16816(pvacc[2 * j + 1], pah, vhf + 2);
                mma16816(pvacc[2 * j],     pah, vlf + 0);
                mma16816(pvacc[2 * j + 1], pah, vlf + 2);
                mma16816(pvacc[2 * j],     pal, vhf + 0);
                mma16816(pvacc[2 * j + 1], pal, vhf + 2);
            }
        }

        // ---- softmax phase 2 (overlaps PV MMA stream): alpha, rs, merge ----
#pragma unroll
        for (int h = 0; h < 2; h++) {
            const float alpha = exp2f(m_i[h] - mn[h]);
            m_i[h] = mn[h];
            float rs = 0.f;
#pragma unroll
            for (int t = 0; t < 8; t++)
                rs += sc[t][2 * h] + sc[t][2 * h + 1];
            rs += __shfl_xor_sync(0xffffffffu, rs, 1);
            rs += __shfl_xor_sync(0xffffffffu, rs, 2);
            l_i[h] = l_i[h] * alpha + rs;
#pragma unroll
            for (int t = 0; t < 8; t++) {
                oac[t][2 * h]     = oac[t][2 * h]     * alpha + pvacc[t][2 * h];
                oac[t][2 * h + 1] = oac[t][2 * h + 1] * alpha + pvacc[t][2 * h + 1];
            }
        }
    }

    // ---- epilogue: ctx fp16 hi/lo ----
    const int bb_ = bh >> 4, hh = bh & 15;
#pragma unroll
    for (int h = 0; h < 2; h++) {
        const float invl = 1.f / l_i[h];
        const int rg = qbase + rb + (lane >> 2) + 8 * h;
        const size_t mrow = (size_t)(bb_ * 2048 + rg) * 1024;
#pragma unroll
        for (int t = 0; t < 8; t++) {
            const float v0 = oac[t][2 * h] * invl;
            const float v1 = oac[t][2 * h + 1] * invl;
            const int col = hh * 64 + t * 8 + 2 * (lane & 3);
            uint32_t hi, lo;
            split2h(v0, v1, hi, lo);
            *(uint32_t*)(Ohi + mrow + col) = hi;
            *(uint32_t*)(Olo + mrow + col) = lo;
        }
    }
}

// ---------------------------------------------------------------------------
extern "C" void kernel_launch(void* const* d_in, const int* in_sizes, int n_in,
                              void* d_out, int out_size)
{
    const float* x  = (const float*)d_in[0];
    const float* Wq = (const float*)d_in[2];
    const float* bq = (const float*)d_in[3];
    const float* Wk = (const float*)d_in[4];
    const float* bk = (const float*)d_in[5];
    const float* Wv = (const float*)d_in[6];
    const float* bv = (const float*)d_in[7];
    const float* Wo = (const float*)d_in[8];
    const float* bo = (const float*)d_in[9];

    __half *xh, *xl, *wth, *wtl;
    __nv_bfloat16 *qh, *ql, *kh, *kl, *vh, *vl;
    cudaGetSymbolAddress((void**)&xh, g_Xhi);
    cudaGetSymbolAddress((void**)&xl, g_Xlo);
    cudaGetSymbolAddress((void**)&wth, g_Wth);
    cudaGetSymbolAddress((void**)&wtl, g_Wtl);
    cudaGetSymbolAddress((void**)&qh, g_Qh);
    cudaGetSymbolAddress((void**)&ql, g_Ql);
    cudaGetSymbolAddress((void**)&kh, g_Kh);
    cudaGetSymbolAddress((void**)&kl, g_Kl);
    cudaGetSymbolAddress((void**)&vh, g_Vh);
    cudaGetSymbolAddress((void**)&vl, g_Vl);

    const int n4 = M_ROWS * D_ / 4;
    const dim3 tb(32, 32);

    cudaFuncSetAttribute(gemm_tc, cudaFuncAttributeMaxDynamicSharedMemorySize, GSMEM);
    cudaFuncSetAttribute(flash_attn_tc, cudaFuncAttributeMaxDynamicSharedMemorySize, ASMEM);

    split_f16<<<(n4 + 255) / 256, 256>>>(x, xh, xl, n4);
    transpose_split<<<dim3(32, 32, 3), tb>>>(Wq, Wk, Wv, wth, wtl);

    gemm_tc<<<dim3(24, 32), 256, GSMEM>>>(xh, xl, wth, wtl, bq, bk, bv,
                                          nullptr, qh, ql, kh, kl, vh, vl, 1);

    // transpose Wo before attention (wth/wtl free after QKV GEMM)
    transpose_split<<<dim3(32, 32, 1), tb>>>(Wo, Wo, Wo, wth, wtl);

    flash_attn_tc<<<dim3(32, BH_), 128, ASMEM>>>(qh, ql, kh, kl, vh, vl, xh, xl);

    gemm_tc<<<dim3(8, 32), 256, GSMEM>>>(xh, xl, wth, wtl, bo, bo, bo,
                                         (float*)d_out, nullptr, nullptr,
                                         nullptr, nullptr, nullptr, nullptr, 0);
}